// round 1
// baseline (speedup 1.0000x reference)
#include <cuda_runtime.h>
#include <math.h>
#include <stdint.h>

// Shapes (fixed by the problem)
#define B_SZ  8192
#define S_IN  4096
#define S_OUT 4096
#define H     128

// h2 scratch (8192 x 128 f32 = 4 MB) — __device__ global, no allocation.
__device__ float g_h2[B_SZ * H];

// ---------------------------------------------------------------------------
// tf32 helpers
// ---------------------------------------------------------------------------
__device__ __forceinline__ uint32_t f2tf32(float f) {
    uint32_t u;
    asm("cvt.rna.tf32.f32 %0, %1;" : "=r"(u) : "f"(f));
    return u;
}
__device__ __forceinline__ uint4 tf32x4(float4 v) {
    uint4 r;
    r.x = f2tf32(v.x); r.y = f2tf32(v.y); r.z = f2tf32(v.z); r.w = f2tf32(v.w);
    return r;
}
// mma.m16n8k8 row.col tf32*tf32 -> f32, D==C accumulate
__device__ __forceinline__ void mma8(float* c, const uint32_t* a, const uint32_t* b) {
    asm volatile(
        "mma.sync.aligned.m16n8k8.row.col.f32.tf32.tf32.f32 "
        "{%0,%1,%2,%3}, {%4,%5,%6,%7}, {%8,%9}, {%0,%1,%2,%3};"
        : "+f"(c[0]), "+f"(c[1]), "+f"(c[2]), "+f"(c[3])
        : "r"(a[0]), "r"(a[1]), "r"(a[2]), "r"(a[3]), "r"(b[0]), "r"(b[1]));
}

// ---------------------------------------------------------------------------
// Kernel 1: AR(7) IIR filter. One thread per batch row; writes ar into d_out.
// ar[t] = noise[t] + sum_{i=0..6} ar[t-1-i]*c[i]  (t >= 7; zero before).
// 28-step unroll (28 % 7 == 0) => shift register fully renames to registers.
// ---------------------------------------------------------------------------
__global__ __launch_bounds__(64) void ar_kernel(const float* __restrict__ noise,
                                                const float* __restrict__ coef,
                                                float* __restrict__ out) {
    int r = blockIdx.x * 64 + threadIdx.x;          // 128 blocks * 64 = 8192 rows
    const float* nr = noise + (size_t)r * S_OUT;
    float* orow = out + (size_t)r * S_OUT;

    float cc[7];
#pragma unroll
    for (int i = 0; i < 7; ++i) cc[i] = __ldg(&coef[i]);

    float y7 = nr[7];                               // ar[7] = noise[7]
    ((float4*)orow)[0] = make_float4(0.f, 0.f, 0.f, 0.f);
    ((float4*)orow)[1] = make_float4(0.f, 0.f, 0.f, y7);

    // slot[t % 7] holds ar[t]; times 1..7 => slots 1..6 zero, slot 0 = y7
    float sl[7] = {y7, 0.f, 0.f, 0.f, 0.f, 0.f, 0.f};

    // t = 8 .. 4095 : 4088 = 146 * 28 steps
    for (int it = 0; it < 146; ++it) {
        const float4* np = (const float4*)(nr + 8 + it * 28);
        float4 nv4[7];
#pragma unroll
        for (int q = 0; q < 7; ++q) nv4[q] = np[q];
        const float* nv = (const float*)nv4;
        float ov[28];
#pragma unroll
        for (int j = 0; j < 28; ++j) {
            // t = 8 + it*28 + j  =>  t % 7 == (1 + j) % 7
            float v = nv[j];
#pragma unroll
            for (int i = 0; i < 7; ++i) v = fmaf(cc[i], sl[(j - i + 14) % 7], v);
            sl[(j + 1) % 7] = v;
            ov[j] = v;
        }
        float4* op = (float4*)(orow + 8 + it * 28);
#pragma unroll
        for (int q = 0; q < 7; ++q) op[q] = ((const float4*)ov)[q];
    }
}

// ---------------------------------------------------------------------------
// Kernel 2: fused MLP front: h2 = relu(relu(x@W1^T + b1)@W2^T + b2) -> g_h2
// GEMM1: M=8192 (BM=64/block), N=128, K=4096, tf32 mma, double-buffered smem.
// GEMM2 (K=128) fused: h1 tile stays in smem.
// Block: 256 threads = 8 warps, warp grid 2(m) x 4(n), warp tile 32x32.
// Manual smem layout (45056 B static):
//   [0,10240)      As[2][64][20]   (tf32, stride 20 => conflict-free frags)
//   [10240,30720)  Bs[2][128][20]
//   [0,33792)      h1s[64][132]    (reused after GEMM1; stride 132 conflict-free)
//   [33792,44032)  W2s[128][20]
//   [44032,45056)  b1s[128], b2s[128]
// ---------------------------------------------------------------------------
__global__ __launch_bounds__(256) void mlp12_kernel(const float* __restrict__ x,
                                                    const float* __restrict__ W1,
                                                    const float* __restrict__ b1,
                                                    const float* __restrict__ W2,
                                                    const float* __restrict__ b2) {
    __shared__ __align__(16) unsigned char smem_raw[45056];
    uint32_t (*As)[64][20]  = reinterpret_cast<uint32_t(*)[64][20]>(smem_raw);
    uint32_t (*Bs)[128][20] = reinterpret_cast<uint32_t(*)[128][20]>(smem_raw + 10240);
    uint32_t (*h1s)[132]    = reinterpret_cast<uint32_t(*)[132]>(smem_raw);
    uint32_t (*W2s)[20]     = reinterpret_cast<uint32_t(*)[20]>(smem_raw + 33792);
    float* b1s = reinterpret_cast<float*>(smem_raw + 44032);
    float* b2s = b1s + 128;

    const int tid  = threadIdx.x;
    const int warp = tid >> 5, lane = tid & 31;
    const int g    = lane >> 2, tig = lane & 3;
    const int wm0  = (warp >> 2) * 32;   // 0 or 32
    const int wn0  = (warp & 3) * 32;    // 0,32,64,96
    const int bm0  = blockIdx.x * 64;

    if (tid < 128) { b1s[tid] = b1[tid]; b2s[tid] = b2[tid]; }

    const int lrow = tid >> 2;               // 0..63
    const int lkq  = (tid & 3) << 2;         // 0,4,8,12
    const float* gA  = x  + (size_t)(bm0 + lrow) * S_IN + lkq;
    const float* gB0 = W1 + (size_t)lrow * S_IN + lkq;          // rows 0..63
    const float* gB1 = W1 + (size_t)(lrow + 64) * S_IN + lkq;   // rows 64..127

    float c[2][4][4];
#pragma unroll
    for (int mt = 0; mt < 2; ++mt)
#pragma unroll
        for (int nt = 0; nt < 4; ++nt)
#pragma unroll
            for (int i = 0; i < 4; ++i) c[mt][nt][i] = 0.f;

    // ---- GEMM1 main loop (K = 4096, BK = 16, 256 iters, double buffered) ----
    {
        float4 av = *(const float4*)gA;
        float4 b0v = *(const float4*)gB0;
        float4 b1v = *(const float4*)gB1;
        *(uint4*)&As[0][lrow][lkq]        = tf32x4(av);
        *(uint4*)&Bs[0][lrow][lkq]        = tf32x4(b0v);
        *(uint4*)&Bs[0][lrow + 64][lkq]   = tf32x4(b1v);
    }
    __syncthreads();

    for (int kt = 0; kt < 256; ++kt) {
        const int cur = kt & 1;
        float4 nav, nb0, nb1;
        if (kt + 1 < 256) {
            const int k0 = (kt + 1) * 16;
            nav = *(const float4*)(gA  + k0);
            nb0 = *(const float4*)(gB0 + k0);
            nb1 = *(const float4*)(gB1 + k0);
        }
#pragma unroll
        for (int ks = 0; ks < 2; ++ks) {
            const int kb = ks * 8;
            uint32_t a[2][4], bf[4][2];
#pragma unroll
            for (int mt = 0; mt < 2; ++mt) {
                const int m = wm0 + mt * 16 + g;
                a[mt][0] = As[cur][m][kb + tig];
                a[mt][1] = As[cur][m + 8][kb + tig];
                a[mt][2] = As[cur][m][kb + tig + 4];
                a[mt][3] = As[cur][m + 8][kb + tig + 4];
            }
#pragma unroll
            for (int nt = 0; nt < 4; ++nt) {
                const int n = wn0 + nt * 8 + g;
                bf[nt][0] = Bs[cur][n][kb + tig];
                bf[nt][1] = Bs[cur][n][kb + tig + 4];
            }
#pragma unroll
            for (int mt = 0; mt < 2; ++mt)
#pragma unroll
                for (int nt = 0; nt < 4; ++nt) mma8(c[mt][nt], a[mt], bf[nt]);
        }
        if (kt + 1 < 256) {
            const int nb = cur ^ 1;
            *(uint4*)&As[nb][lrow][lkq]      = tf32x4(nav);
            *(uint4*)&Bs[nb][lrow][lkq]      = tf32x4(nb0);
            *(uint4*)&Bs[nb][lrow + 64][lkq] = tf32x4(nb1);
        }
        __syncthreads();
    }

    // ---- h1 = relu(c + b1) -> h1s (tf32), overwrites As/Bs (all reads done) --
#pragma unroll
    for (int mt = 0; mt < 2; ++mt)
#pragma unroll
        for (int nt = 0; nt < 4; ++nt) {
            const int row = wm0 + mt * 16 + g;
            const int col = wn0 + nt * 8 + 2 * tig;
            float v0 = fmaxf(c[mt][nt][0] + b1s[col], 0.f);
            float v1 = fmaxf(c[mt][nt][1] + b1s[col + 1], 0.f);
            float v2 = fmaxf(c[mt][nt][2] + b1s[col], 0.f);
            float v3 = fmaxf(c[mt][nt][3] + b1s[col + 1], 0.f);
            uint2 p0; p0.x = f2tf32(v0); p0.y = f2tf32(v1);
            uint2 p1; p1.x = f2tf32(v2); p1.y = f2tf32(v3);
            *(uint2*)&h1s[row][col]     = p0;
            *(uint2*)&h1s[row + 8][col] = p1;
        }
    __syncthreads();

    // ---- GEMM2: h2 = relu(h1 @ W2^T + b2), K=128 in 8 chunks of 16 ----------
#pragma unroll
    for (int mt = 0; mt < 2; ++mt)
#pragma unroll
        for (int nt = 0; nt < 4; ++nt)
#pragma unroll
            for (int i = 0; i < 4; ++i) c[mt][nt][i] = 0.f;

    for (int kt2 = 0; kt2 < 8; ++kt2) {
        const int k0 = kt2 * 16;
        float4 w0 = *(const float4*)(W2 + (size_t)lrow * H + k0 + lkq);
        float4 w1 = *(const float4*)(W2 + (size_t)(lrow + 64) * H + k0 + lkq);
        __syncthreads();   // previous chunk's W2s reads done
        *(uint4*)&W2s[lrow][lkq]      = tf32x4(w0);
        *(uint4*)&W2s[lrow + 64][lkq] = tf32x4(w1);
        __syncthreads();
#pragma unroll
        for (int ks = 0; ks < 2; ++ks) {
            const int kb = ks * 8;          // within W2s chunk
            const int kh = k0 + kb;         // within h1s (absolute k)
            uint32_t a[2][4], bf[4][2];
#pragma unroll
            for (int mt = 0; mt < 2; ++mt) {
                const int m = wm0 + mt * 16 + g;
                a[mt][0] = h1s[m][kh + tig];
                a[mt][1] = h1s[m + 8][kh + tig];
                a[mt][2] = h1s[m][kh + tig + 4];
                a[mt][3] = h1s[m + 8][kh + tig + 4];
            }
#pragma unroll
            for (int nt = 0; nt < 4; ++nt) {
                const int n = wn0 + nt * 8 + g;
                bf[nt][0] = W2s[n][kb + tig];
                bf[nt][1] = W2s[n][kb + tig + 4];
            }
#pragma unroll
            for (int mt = 0; mt < 2; ++mt)
#pragma unroll
                for (int nt = 0; nt < 4; ++nt) mma8(c[mt][nt], a[mt], bf[nt]);
        }
    }

    // ---- epilogue: h2 -> g_h2 ----------------------------------------------
#pragma unroll
    for (int mt = 0; mt < 2; ++mt)
#pragma unroll
        for (int nt = 0; nt < 4; ++nt) {
            const int row = wm0 + mt * 16 + g;
            const int col = wn0 + nt * 8 + 2 * tig;
            float2 q0, q1;
            q0.x = fmaxf(c[mt][nt][0] + b2s[col], 0.f);
            q0.y = fmaxf(c[mt][nt][1] + b2s[col + 1], 0.f);
            q1.x = fmaxf(c[mt][nt][2] + b2s[col], 0.f);
            q1.y = fmaxf(c[mt][nt][3] + b2s[col + 1], 0.f);
            *(float2*)&g_h2[(size_t)(bm0 + row) * H + col]     = q0;
            *(float2*)&g_h2[(size_t)(bm0 + row + 8) * H + col] = q1;
        }
}

// ---------------------------------------------------------------------------
// Kernel 3: out = tanh(h2 @ W3^T + b3) + out   (out already holds AR)
// M=8192, N=4096, K=128. BM=BN=128, 2048 blocks. Warp tile 64x32 (MT=4,NT=4).
// ---------------------------------------------------------------------------
__global__ __launch_bounds__(256) void gemm3_kernel(const float* __restrict__ W3,
                                                    const float* __restrict__ b3,
                                                    float* __restrict__ out) {
    __shared__ __align__(16) uint32_t As3[2][128][20];
    __shared__ __align__(16) uint32_t Bs3[2][128][20];
    __shared__ float b3s[128];

    const int tid  = threadIdx.x;
    const int warp = tid >> 5, lane = tid & 31;
    const int g    = lane >> 2, tig = lane & 3;
    const int wm0  = (warp >> 2) * 64;   // 0 or 64
    const int wn0  = (warp & 3) * 32;    // 0,32,64,96
    const int bm0  = blockIdx.y * 128;
    const int bn0  = blockIdx.x * 128;

    if (tid < 128) b3s[tid] = b3[bn0 + tid];

    const int lrow = tid >> 2;           // 0..63
    const int lkq  = (tid & 3) << 2;
    const float* gA0 = g_h2 + (size_t)(bm0 + lrow) * H + lkq;
    const float* gA1 = gA0 + (size_t)64 * H;
    const float* gB0 = W3 + (size_t)(bn0 + lrow) * H + lkq;
    const float* gB1 = gB0 + (size_t)64 * H;

    float c[4][4][4];
#pragma unroll
    for (int mt = 0; mt < 4; ++mt)
#pragma unroll
        for (int nt = 0; nt < 4; ++nt)
#pragma unroll
            for (int i = 0; i < 4; ++i) c[mt][nt][i] = 0.f;

    {
        float4 a0 = *(const float4*)gA0;
        float4 a1 = *(const float4*)gA1;
        float4 w0 = *(const float4*)gB0;
        float4 w1 = *(const float4*)gB1;
        *(uint4*)&As3[0][lrow][lkq]      = tf32x4(a0);
        *(uint4*)&As3[0][lrow + 64][lkq] = tf32x4(a1);
        *(uint4*)&Bs3[0][lrow][lkq]      = tf32x4(w0);
        *(uint4*)&Bs3[0][lrow + 64][lkq] = tf32x4(w1);
    }
    __syncthreads();

    for (int kt = 0; kt < 8; ++kt) {
        const int cur = kt & 1;
        float4 na0, na1, nw0, nw1;
        if (kt + 1 < 8) {
            const int k0 = (kt + 1) * 16;
            na0 = *(const float4*)(gA0 + k0);
            na1 = *(const float4*)(gA1 + k0);
            nw0 = *(const float4*)(gB0 + k0);
            nw1 = *(const float4*)(gB1 + k0);
        }
#pragma unroll
        for (int ks = 0; ks < 2; ++ks) {
            const int kb = ks * 8;
            uint32_t a[4][4], bf[4][2];
#pragma unroll
            for (int mt = 0; mt < 4; ++mt) {
                const int m = wm0 + mt * 16 + g;
                a[mt][0] = As3[cur][m][kb + tig];
                a[mt][1] = As3[cur][m + 8][kb + tig];
                a[mt][2] = As3[cur][m][kb + tig + 4];
                a[mt][3] = As3[cur][m + 8][kb + tig + 4];
            }
#pragma unroll
            for (int nt = 0; nt < 4; ++nt) {
                const int n = wn0 + nt * 8 + g;
                bf[nt][0] = Bs3[cur][n][kb + tig];
                bf[nt][1] = Bs3[cur][n][kb + tig + 4];
            }
#pragma unroll
            for (int mt = 0; mt < 4; ++mt)
#pragma unroll
                for (int nt = 0; nt < 4; ++nt) mma8(c[mt][nt], a[mt], bf[nt]);
        }
        if (kt + 1 < 8) {
            const int nb = cur ^ 1;
            *(uint4*)&As3[nb][lrow][lkq]      = tf32x4(na0);
            *(uint4*)&As3[nb][lrow + 64][lkq] = tf32x4(na1);
            *(uint4*)&Bs3[nb][lrow][lkq]      = tf32x4(nw0);
            *(uint4*)&Bs3[nb][lrow + 64][lkq] = tf32x4(nw1);
        }
        __syncthreads();
    }

    // epilogue: tanh(acc + b3) + ar (RMW d_out)
#pragma unroll
    for (int mt = 0; mt < 4; ++mt)
#pragma unroll
        for (int nt = 0; nt < 4; ++nt) {
            const int row = wm0 + mt * 16 + g;
            const int col = wn0 + nt * 8 + 2 * tig;
            size_t o0 = (size_t)(bm0 + row) * S_OUT + bn0 + col;
            float2 ar0 = *(float2*)&out[o0];
            float2 r0;
            r0.x = tanhf(c[mt][nt][0] + b3s[col]) + ar0.x;
            r0.y = tanhf(c[mt][nt][1] + b3s[col + 1]) + ar0.y;
            *(float2*)&out[o0] = r0;
            size_t o1 = o0 + (size_t)8 * S_OUT;
            float2 ar1 = *(float2*)&out[o1];
            float2 r1;
            r1.x = tanhf(c[mt][nt][2] + b3s[col]) + ar1.x;
            r1.y = tanhf(c[mt][nt][3] + b3s[col + 1]) + ar1.y;
            *(float2*)&out[o1] = r1;
        }
}

// ---------------------------------------------------------------------------
// Launch: ar -> out; mlp12 -> g_h2; gemm3 reads g_h2 + out, writes out.
// Inputs (metadata order): x, noise, W1, b1, W2, b2, W3, b3, ar_coef
// ---------------------------------------------------------------------------
extern "C" void kernel_launch(void* const* d_in, const int* in_sizes, int n_in,
                              void* d_out, int out_size) {
    const float* x     = (const float*)d_in[0];
    const float* noise = (const float*)d_in[1];
    const float* W1    = (const float*)d_in[2];
    const float* b1    = (const float*)d_in[3];
    const float* W2    = (const float*)d_in[4];
    const float* b2    = (const float*)d_in[5];
    const float* W3    = (const float*)d_in[6];
    const float* b3    = (const float*)d_in[7];
    const float* arc   = (const float*)d_in[8];
    float* out = (float*)d_out;

    ar_kernel<<<128, 64>>>(noise, arc, out);
    mlp12_kernel<<<128, 256>>>(x, W1, b1, W2, b2);
    gemm3_kernel<<<dim3(32, 64), 256>>>(W3, b3, out);
}